// round 5
// baseline (speedup 1.0000x reference)
#include <cuda_runtime.h>
#include <math.h>

#define BATCH 2
#define NSEQ 2048
#define DIM 1024
#define NH 16
#define HD 64
#define ROWS (BATCH*NSEQ)          // 4096
#define BELEMS (NSEQ*DIM)          // 2097152

// ---------------- device scratch (static allocation = allowed) ----------------
__device__ double g_xpart_s[BATCH*64], g_xpart_q[BATCH*64];
__device__ double g_wpart[5*64];
__device__ double g_zpart_s[ROWS], g_zpart_q[ROWS];
__device__ float  g_xmu[BATCH], g_xrstd[BATCH];
__device__ float  g_zmu[BATCH], g_zrstd[BATCH];
__device__ float  g_wm[5];                       // clipped mean|w|
__device__ float  g_A [ROWS*DIM];                // dequantized act of x
__device__ float  g_A2[ROWS*DIM];                // dequantized act of z
__device__ float  g_W [5*DIM*DIM];               // dequantized ternary weights
__device__ float  g_Q [BATCH*NH*NSEQ*HD];
__device__ float  g_K [BATCH*NH*NSEQ*HD];
__device__ float  g_V [BATCH*NH*NSEQ*HD];
__device__ float  g_G [ROWS*DIM];                // silu(gate)
__device__ float  g_Y [ROWS*DIM];                // attention output [b,n,h*64+d]
__device__ float  g_Z [ROWS*DIM];                // ln(y)*g
__device__ float  g_decay[NH*NSEQ];

// ---------------- batch stats of x (deterministic, double) ----------------
__global__ void k_reduce_x(const float* __restrict__ x) {
    int b = blockIdx.y;
    const float* p = x + (size_t)b * BELEMS;
    double s = 0.0, q = 0.0;
    for (int i = blockIdx.x * blockDim.x + threadIdx.x; i < BELEMS;
         i += gridDim.x * blockDim.x) {
        double v = (double)p[i];
        s += v; q += v * v;
    }
    __shared__ double shs[256], shq[256];
    shs[threadIdx.x] = s; shq[threadIdx.x] = q; __syncthreads();
    for (int o = 128; o > 0; o >>= 1) {
        if (threadIdx.x < o) {
            shs[threadIdx.x] += shs[threadIdx.x + o];
            shq[threadIdx.x] += shq[threadIdx.x + o];
        }
        __syncthreads();
    }
    if (threadIdx.x == 0) {
        g_xpart_s[b * 64 + blockIdx.x] = shs[0];
        g_xpart_q[b * 64 + blockIdx.x] = shq[0];
    }
}

// ---------------- sum |w| for all 5 weights ----------------
__global__ void k_reduce_wabs(const float* a, const float* b2, const float* c,
                              const float* d, const float* e) {
    const float* ws[5] = {a, b2, c, d, e};
    const float* w = ws[blockIdx.y];
    double s = 0.0;
    for (int i = blockIdx.x * blockDim.x + threadIdx.x; i < DIM * DIM;
         i += gridDim.x * blockDim.x)
        s += (double)fabsf(w[i]);
    __shared__ double sh[256];
    sh[threadIdx.x] = s; __syncthreads();
    for (int o = 128; o > 0; o >>= 1) {
        if (threadIdx.x < o) sh[threadIdx.x] += sh[threadIdx.x + o];
        __syncthreads();
    }
    if (threadIdx.x == 0) g_wpart[blockIdx.y * 64 + blockIdx.x] = sh[0];
}

// ---------------- finalize x stats + weight scales ----------------
__global__ void k_fin1() {
    int t = threadIdx.x;
    if (t < BATCH) {
        double s = 0.0, q = 0.0;
        for (int i = 0; i < 64; i++) { s += g_xpart_s[t*64+i]; q += g_xpart_q[t*64+i]; }
        double n = (double)BELEMS;
        double mu = s / n;
        double var = q / n - mu * mu;
        g_xmu[t]   = (float)mu;
        g_xrstd[t] = (float)(1.0 / sqrt(var + 1e-5));
    }
    if (t >= 8 && t < 13) {
        int wi = t - 8;
        double s = 0.0;
        for (int i = 0; i < 64; i++) s += g_wpart[wi*64+i];
        float m = (float)(s / (double)(DIM * DIM));
        if (m < 1e-5f) m = 1e-5f;
        g_wm[wi] = m;
    }
}

// ---------------- ternarize weights (mimic ref's /scale chain) ----------------
__global__ void k_tern(const float* a, const float* b2, const float* c,
                       const float* d, const float* e) {
    const float* ws[5] = {a, b2, c, d, e};
    int wi = blockIdx.y;
    const float* w = ws[wi];
    float sc = 1.0f / g_wm[wi];          // scale = 1/clip(mean,1e-5)
    float* out = g_W + (size_t)wi * DIM * DIM;
    for (int i = blockIdx.x * blockDim.x + threadIdx.x; i < DIM * DIM;
         i += gridDim.x * blockDim.x) {
        float t = rintf(w[i] * sc);
        t = fminf(fmaxf(t, -1.0f), 1.0f);
        out[i] = t / sc;
    }
}

// ---------------- per-row activation quant (dequantized output) ----------------
__global__ void k_qact(const float* __restrict__ xin, int sel) {
    int row = blockIdx.x;
    int b = row >> 11;
    float mu = sel ? g_zmu[b]   : g_xmu[b];
    float rs = sel ? g_zrstd[b] : g_xrstd[b];
    const float* p = (sel ? (const float*)g_Z : xin) + (size_t)row * DIM;
    float* op = (sel ? g_A2 : g_A) + (size_t)row * DIM;

    int c0 = threadIdx.x * 4;
    float4 vv = *(const float4*)(p + c0);
    float v0 = (vv.x - mu) * rs, v1 = (vv.y - mu) * rs;
    float v2 = (vv.z - mu) * rs, v3 = (vv.w - mu) * rs;
    float mx = fmaxf(fmaxf(fabsf(v0), fabsf(v1)), fmaxf(fabsf(v2), fabsf(v3)));

    __shared__ float sh[256];
    sh[threadIdx.x] = mx; __syncthreads();
    for (int o = 128; o > 0; o >>= 1) {
        if (threadIdx.x < o) sh[threadIdx.x] = fmaxf(sh[threadIdx.x], sh[threadIdx.x + o]);
        __syncthreads();
    }
    float maxc  = fmaxf(sh[0], 1e-5f);
    float scale = 127.0f / maxc;

    float4 o4;
    o4.x = fminf(fmaxf(rintf(v0 * scale), -128.0f), 127.0f) / scale;
    o4.y = fminf(fmaxf(rintf(v1 * scale), -128.0f), 127.0f) / scale;
    o4.z = fminf(fmaxf(rintf(v2 * scale), -128.0f), 127.0f) / scale;
    o4.w = fminf(fmaxf(rintf(v3 * scale), -128.0f), 127.0f) / scale;
    *(float4*)(op + c0) = o4;
}

// ---------------- decay table: gamma_h^d in double ----------------
__global__ void k_decay() {
    int h = blockIdx.x;
    double a = log(1.0 / 32.0), bq = log(1.0 / 512.0);
    double lin = a + (bq - a) * ((double)h / 15.0);
    double gamma = 1.0 - exp(lin);
    double lg = log(gamma);
    for (int d = threadIdx.x; d < NSEQ; d += blockDim.x)
        g_decay[h * NSEQ + d] = (float)exp(lg * (double)d);
}

// ---------------- SGEMM-NT 128x128x16, 8x8/thread ----------------
// mode 0..3: A=g_A, W=g_W[mode]; epilogue Q/K/V (head layout) or silu->G
// mode 4   : A=g_A2, W=g_W[4];   epilogue -> dst (d_out)
__global__ void __launch_bounds__(256) k_gemm(int baseMode, float* __restrict__ dst) {
    int mode = baseMode + blockIdx.z;
    const float* A = (mode == 4) ? g_A2 : g_A;
    const float* W = g_W + (size_t)mode * DIM * DIM;

    __shared__ float As[16 * 132];
    __shared__ float Bs[16 * 132];

    int tid = threadIdx.x;
    int tm = tid >> 4, tn = tid & 15;
    const float* Ab = A + (size_t)blockIdx.y * 128 * DIM;
    const float* Wb = W + (size_t)blockIdx.x * 128 * DIM;

    int lr = tid >> 2;             // 0..63
    int lc = (tid & 3) << 2;       // 0,4,8,12

    float acc[8][8];
    #pragma unroll
    for (int i = 0; i < 8; i++)
        #pragma unroll
        for (int j = 0; j < 8; j++) acc[i][j] = 0.0f;

    for (int kt = 0; kt < 64; ++kt) {
        int k0 = kt * 16;
        float4 a0 = *(const float4*)(Ab + (size_t)lr        * DIM + k0 + lc);
        float4 a1 = *(const float4*)(Ab + (size_t)(lr + 64) * DIM + k0 + lc);
        float4 b0 = *(const float4*)(Wb + (size_t)lr        * DIM + k0 + lc);
        float4 b1 = *(const float4*)(Wb + (size_t)(lr + 64) * DIM + k0 + lc);
        __syncthreads();
        As[(lc+0)*132 + lr] = a0.x; As[(lc+1)*132 + lr] = a0.y;
        As[(lc+2)*132 + lr] = a0.z; As[(lc+3)*132 + lr] = a0.w;
        As[(lc+0)*132 + lr+64] = a1.x; As[(lc+1)*132 + lr+64] = a1.y;
        As[(lc+2)*132 + lr+64] = a1.z; As[(lc+3)*132 + lr+64] = a1.w;
        Bs[(lc+0)*132 + lr] = b0.x; Bs[(lc+1)*132 + lr] = b0.y;
        Bs[(lc+2)*132 + lr] = b0.z; Bs[(lc+3)*132 + lr] = b0.w;
        Bs[(lc+0)*132 + lr+64] = b1.x; Bs[(lc+1)*132 + lr+64] = b1.y;
        Bs[(lc+2)*132 + lr+64] = b1.z; Bs[(lc+3)*132 + lr+64] = b1.w;
        __syncthreads();

        #pragma unroll
        for (int k = 0; k < 16; k++) {
            float ra[8], rb[8];
            float4 t0 = *(const float4*)&As[k*132 + tm*8];
            float4 t1 = *(const float4*)&As[k*132 + tm*8 + 4];
            ra[0]=t0.x; ra[1]=t0.y; ra[2]=t0.z; ra[3]=t0.w;
            ra[4]=t1.x; ra[5]=t1.y; ra[6]=t1.z; ra[7]=t1.w;
            float4 u0 = *(const float4*)&Bs[k*132 + tn*8];
            float4 u1 = *(const float4*)&Bs[k*132 + tn*8 + 4];
            rb[0]=u0.x; rb[1]=u0.y; rb[2]=u0.z; rb[3]=u0.w;
            rb[4]=u1.x; rb[5]=u1.y; rb[6]=u1.z; rb[7]=u1.w;
            #pragma unroll
            for (int i = 0; i < 8; i++)
                #pragma unroll
                for (int j = 0; j < 8; j++)
                    acc[i][j] += ra[i] * rb[j];
        }
    }

    int m0 = blockIdx.y * 128 + tm * 8;
    int n0 = blockIdx.x * 128 + tn * 8;
    if (mode <= 2) {
        float* dp = (mode == 0) ? g_Q : (mode == 1) ? g_K : g_V;
        #pragma unroll
        for (int i = 0; i < 8; i++) {
            int m = m0 + i;
            int bb = m >> 11, ns = m & 2047;
            #pragma unroll
            for (int j = 0; j < 8; j++) {
                int n = n0 + j;
                int hh = n >> 6, dd = n & 63;
                dp[(((size_t)(bb*NH + hh))*NSEQ + ns)*HD + dd] = acc[i][j];
            }
        }
    } else if (mode == 3) {
        #pragma unroll
        for (int i = 0; i < 8; i++)
            #pragma unroll
            for (int j = 0; j < 8; j++) {
                float c = acc[i][j];
                g_G[(size_t)(m0+i)*DIM + n0 + j] = c / (1.0f + expf(-c));
            }
    } else {
        #pragma unroll
        for (int i = 0; i < 8; i++)
            #pragma unroll
            for (int j = 0; j < 8; j++)
                dst[(size_t)(m0+i)*DIM + n0 + j] = acc[i][j];
    }
}

// ---------------- retention attention ----------------
// grid: (N/64, H, B), 256 threads, 4x4 per thread.
__global__ void __launch_bounds__(256) k_attn() {
    int nt = blockIdx.x, h = blockIdx.y, b = blockIdx.z;
    int n0 = nt * 64;
    size_t base = ((size_t)(b * NH + h)) * NSEQ * HD;
    const float* Qp = g_Q + base;
    const float* Kp = g_K + base;
    const float* Vp = g_V + base;
    const float* dec = g_decay + (size_t)h * NSEQ;

    __shared__ float Qs[64 * 65];   // transposed: [dd][r]
    __shared__ float KS[64 * 65];   // K transposed [dd][m], later S as [m][r]
    __shared__ float Vs[32 * 65];   // natural [m][dd], half tile

    int tid = threadIdx.x;
    int ty = tid >> 4, tx = tid & 15;
    int r0 = ty * 4, c0 = tx * 4;

    // load Q tile transposed
    for (int i4 = tid; i4 < 1024; i4 += 256) {
        int r = i4 >> 4;
        int d0 = (i4 & 15) << 2;
        float4 qv = *(const float4*)(Qp + (size_t)(n0 + r) * HD + d0);
        Qs[(d0+0)*65 + r] = qv.x; Qs[(d0+1)*65 + r] = qv.y;
        Qs[(d0+2)*65 + r] = qv.z; Qs[(d0+3)*65 + r] = qv.w;
    }

    float yacc[4][4];
    #pragma unroll
    for (int i = 0; i < 4; i++)
        #pragma unroll
        for (int j = 0; j < 4; j++) yacc[i][j] = 0.0f;

    for (int mt = 0; mt <= nt; ++mt) {
        int m0 = mt * 64;
        __syncthreads();   // prior S/V reads done before KS overwrite
        for (int i4 = tid; i4 < 1024; i4 += 256) {
            int r = i4 >> 4;
            int d0 = (i4 & 15) << 2;
            float4 kv = *(const float4*)(Kp + (size_t)(m0 + r) * HD + d0);
            KS[(d0+0)*65 + r] = kv.x; KS[(d0+1)*65 + r] = kv.y;
            KS[(d0+2)*65 + r] = kv.z; KS[(d0+3)*65 + r] = kv.w;
        }
        __syncthreads();

        // phase 1: S = Q K^T
        float s[4][4];
        #pragma unroll
        for (int i = 0; i < 4; i++)
            #pragma unroll
            for (int j = 0; j < 4; j++) s[i][j] = 0.0f;

        #pragma unroll 4
        for (int kk = 0; kk < 64; ++kk) {
            const float* qp = &Qs[kk*65 + r0];
            const float* kp = &KS[kk*65 + c0];
            float q0 = qp[0], q1 = qp[1], q2 = qp[2], q3 = qp[3];
            float k0 = kp[0], k1 = kp[1], k2 = kp[2], k3 = kp[3];
            s[0][0]+=q0*k0; s[0][1]+=q0*k1; s[0][2]+=q0*k2; s[0][3]+=q0*k3;
            s[1][0]+=q1*k0; s[1][1]+=q1*k1; s[1][2]+=q1*k2; s[1][3]+=q1*k3;
            s[2][0]+=q2*k0; s[2][1]+=q2*k1; s[2][2]+=q2*k2; s[2][3]+=q2*k3;
            s[3][0]+=q3*k0; s[3][1]+=q3*k1; s[3][2]+=q3*k2; s[3][3]+=q3*k3;
        }
        __syncthreads();   // all K reads done before overlay

        // decay + causal, store S transposed [m][r] over KS
        #pragma unroll
        for (int i = 0; i < 4; i++)
            #pragma unroll
            for (int j = 0; j < 4; j++) {
                int d = (n0 + r0 + i) - (m0 + c0 + j);
                float val = 0.0f;
                if (d >= 0) val = s[i][j] * 0.125f * dec[d];
                KS[(c0 + j)*65 + r0 + i] = val;
            }
        __syncthreads();

        // phase 2: Y += S V  (two 32-row V chunks)
        #pragma unroll
        for (int half = 0; half < 2; ++half) {
            int mb = half * 32;
            for (int i4 = tid; i4 < 512; i4 += 256) {
                int r = i4 >> 4;
                int d0 = (i4 & 15) << 2;
                float4 vv = *(const float4*)(Vp + (size_t)(m0 + mb + r) * HD + d0);
                float* dv = &Vs[r*65 + d0];
                dv[0] = vv.x; dv[1] = vv.y; dv[2] = vv.z; dv[3] = vv.w;
            }
            __syncthreads();
            #pragma unroll 4
            for (int mm = 0; mm < 32; ++mm) {
                const float* sp = &KS[(mb + mm)*65 + r0];
                const float* vp = &Vs[mm*65 + c0];
                float s0 = sp[0], s1 = sp[1], s2 = sp[2], s3 = sp[3];
                float v0 = vp[0], v1 = vp[1], v2 = vp[2], v3 = vp[3];
                yacc[0][0]+=s0*v0; yacc[0][1]+=s0*v1; yacc[0][2]+=s0*v2; yacc[0][3]+=s0*v3;
                yacc[1][0]+=s1*v0; yacc[1][1]+=s1*v1; yacc[1][2]+=s1*v2; yacc[1][3]+=s1*v3;
                yacc[2][0]+=s2*v0; yacc[2][1]+=s2*v1; yacc[2][2]+=s2*v2; yacc[2][3]+=s2*v3;
                yacc[3][0]+=s3*v0; yacc[3][1]+=s3*v1; yacc[3][2]+=s3*v2; yacc[3][3]+=s3*v3;
            }
            __syncthreads();
        }
    }

    // write y in [b, n, h*64+d] layout
    #pragma unroll
    for (int i = 0; i < 4; i++)
        #pragma unroll
        for (int j = 0; j < 4; j++)
            g_Y[(size_t)(b*NSEQ + n0 + r0 + i)*DIM + h*HD + c0 + j] = yacc[i][j];
}

// ---------------- LN(y)*silu(g) + per-row double partials for z stats ----------------
__global__ void k_lng(const float* __restrict__ lnw, const float* __restrict__ lnb) {
    int row = blockIdx.x;
    const float* y = g_Y + (size_t)row * DIM;
    int c0 = threadIdx.x * 4;
    float4 yv = *(const float4*)(y + c0);

    __shared__ double shs[256], shq[256];
    shs[threadIdx.x] = (double)yv.x + yv.y + yv.z + yv.w;
    shq[threadIdx.x] = (double)yv.x*yv.x + (double)yv.y*yv.y
                     + (double)yv.z*yv.z + (double)yv.w*yv.w;
    __syncthreads();
    for (int o = 128; o > 0; o >>= 1) {
        if (threadIdx.x < o) {
            shs[threadIdx.x] += shs[threadIdx.x + o];
            shq[threadIdx.x] += shq[threadIdx.x + o];
        }
        __syncthreads();
    }
    double mu_d  = shs[0] / (double)DIM;
    double var_d = shq[0] / (double)DIM - mu_d * mu_d;
    float mu = (float)mu_d;
    float rs = (float)(1.0 / sqrt(var_d + 1e-5));
    __syncthreads();

    float4 g4 = *(const float4*)(g_G + (size_t)row * DIM + c0);
    float4 w4 = *(const float4*)(lnw + c0);
    float4 b4 = *(const float4*)(lnb + c0);
    float4 z;
    z.x = ((yv.x - mu) * rs * w4.x + b4.x) * g4.x;
    z.y = ((yv.y - mu) * rs * w4.y + b4.y) * g4.y;
    z.z = ((yv.z - mu) * rs * w4.z + b4.z) * g4.z;
    z.w = ((yv.w - mu) * rs * w4.w + b4.w) * g4.w;
    *(float4*)(g_Z + (size_t)row * DIM + c0) = z;

    // z stats partials (per-row, deterministic)
    shs[threadIdx.x] = (double)z.x + z.y + z.z + z.w;
    shq[threadIdx.x] = (double)z.x*z.x + (double)z.y*z.y
                     + (double)z.z*z.z + (double)z.w*z.w;
    __syncthreads();
    for (int o = 128; o > 0; o >>= 1) {
        if (threadIdx.x < o) {
            shs[threadIdx.x] += shs[threadIdx.x + o];
            shq[threadIdx.x] += shq[threadIdx.x + o];
        }
        __syncthreads();
    }
    if (threadIdx.x == 0) {
        g_zpart_s[row] = shs[0];
        g_zpart_q[row] = shq[0];
    }
}

// ---------------- finalize z batch stats ----------------
__global__ void k_fin2() {
    int b = blockIdx.x;
    double s = 0.0, q = 0.0;
    for (int i = threadIdx.x; i < NSEQ; i += 256) {
        s += g_zpart_s[b * NSEQ + i];
        q += g_zpart_q[b * NSEQ + i];
    }
    __shared__ double shs[256], shq[256];
    shs[threadIdx.x] = s; shq[threadIdx.x] = q; __syncthreads();
    for (int o = 128; o > 0; o >>= 1) {
        if (threadIdx.x < o) {
            shs[threadIdx.x] += shs[threadIdx.x + o];
            shq[threadIdx.x] += shq[threadIdx.x + o];
        }
        __syncthreads();
    }
    if (threadIdx.x == 0) {
        double n = (double)BELEMS;
        double mu = shs[0] / n;
        double var = shq[0] / n - mu * mu;
        g_zmu[b]   = (float)mu;
        g_zrstd[b] = (float)(1.0 / sqrt(var + 1e-5));
    }
}

// ---------------- launch ----------------
extern "C" void kernel_launch(void* const* d_in, const int* in_sizes, int n_in,
                              void* d_out, int out_size) {
    (void)in_sizes; (void)n_in; (void)out_size;
    const float* x   = (const float*)d_in[0];
    const float* wq  = (const float*)d_in[1];
    const float* wk  = (const float*)d_in[2];
    const float* wv  = (const float*)d_in[3];
    const float* wg  = (const float*)d_in[4];
    const float* wo  = (const float*)d_in[5];
    const float* lnw = (const float*)d_in[6];
    const float* lnb = (const float*)d_in[7];
    float* out = (float*)d_out;

    k_reduce_x   <<<dim3(64, BATCH), 256>>>(x);
    k_reduce_wabs<<<dim3(64, 5),     256>>>(wq, wk, wv, wg, wo);
    k_fin1       <<<1, 32>>>();
    k_tern       <<<dim3(256, 5),    256>>>(wq, wk, wv, wg, wo);
    k_qact       <<<ROWS, 256>>>(x, 0);
    k_decay      <<<NH, 256>>>();
    k_gemm       <<<dim3(8, 32, 4),  256>>>(0, out);   // Q,K,V,G
    k_attn       <<<dim3(NSEQ/64, NH, BATCH), 256>>>();
    k_lng        <<<ROWS, 256>>>(lnw, lnb);
    k_fin2       <<<BATCH, 256>>>();
    k_qact       <<<ROWS, 256>>>(x, 1);                // quantize z -> g_A2
    k_gemm       <<<dim3(8, 32, 1),  256>>>(4, out);   // final projection
}

// round 7
// speedup vs baseline: 1.8115x; 1.8115x over previous
#include <cuda_runtime.h>
#include <cuda_bf16.h>
#include <cstdint>
#include <stdint.h>
#include <math.h>

#define BATCH 2
#define NSEQ 2048
#define DIM 1024
#define NH 16
#define HD 64
#define ROWS (BATCH*NSEQ)          // 4096
#define BELEMS (NSEQ*DIM)          // 2097152

// ---------------- device scratch ----------------
__device__ double g_xpart_s[BATCH*64], g_xpart_q[BATCH*64];
__device__ double g_wpart[5*64];
__device__ double g_zpart_s[ROWS], g_zpart_q[ROWS];
__device__ float  g_xmu[BATCH], g_xrstd[BATCH];
__device__ float  g_zmu[BATCH], g_zrstd[BATCH];
__device__ float  g_wsc[5];                      // quant scale (1/mean)
__device__ float  g_wdeq[5];                     // dequant factor (1/scale)
__device__ __nv_bfloat16 g_Aq [ROWS*DIM];        // int-valued quantized act of x
__device__ __nv_bfloat16 g_A2q[ROWS*DIM];        // int-valued quantized act of z
__device__ float  g_arow [ROWS];                 // per-row dequant of x-act
__device__ float  g_a2row[ROWS];                 // per-row dequant of z-act
__device__ __nv_bfloat16 g_Wt[5*DIM*DIM];        // ternary weights {-1,0,1}
__device__ float  g_Q [BATCH*NH*NSEQ*HD];
__device__ float  g_K [BATCH*NH*NSEQ*HD];
__device__ float  g_V [BATCH*NH*NSEQ*HD];
__device__ float  g_G [ROWS*DIM];                // silu(gate)
__device__ float  g_Y [ROWS*DIM];                // attention output [b,n,h*64+d]
__device__ float  g_Z [ROWS*DIM];                // ln(y)*g
__device__ float  g_decay[NH*NSEQ];

// ---------------- batch stats of x (deterministic, double) ----------------
__global__ void k_reduce_x(const float* __restrict__ x) {
    int b = blockIdx.y;
    const float* p = x + (size_t)b * BELEMS;
    double s = 0.0, q = 0.0;
    for (int i = blockIdx.x * blockDim.x + threadIdx.x; i < BELEMS;
         i += gridDim.x * blockDim.x) {
        double v = (double)p[i];
        s += v; q += v * v;
    }
    __shared__ double shs[256], shq[256];
    shs[threadIdx.x] = s; shq[threadIdx.x] = q; __syncthreads();
    for (int o = 128; o > 0; o >>= 1) {
        if (threadIdx.x < o) {
            shs[threadIdx.x] += shs[threadIdx.x + o];
            shq[threadIdx.x] += shq[threadIdx.x + o];
        }
        __syncthreads();
    }
    if (threadIdx.x == 0) {
        g_xpart_s[b * 64 + blockIdx.x] = shs[0];
        g_xpart_q[b * 64 + blockIdx.x] = shq[0];
    }
}

// ---------------- sum |w| for all 5 weights ----------------
__global__ void k_reduce_wabs(const float* a, const float* b2, const float* c,
                              const float* d, const float* e) {
    const float* ws[5] = {a, b2, c, d, e};
    const float* w = ws[blockIdx.y];
    double s = 0.0;
    for (int i = blockIdx.x * blockDim.x + threadIdx.x; i < DIM * DIM;
         i += gridDim.x * blockDim.x)
        s += (double)fabsf(w[i]);
    __shared__ double sh[256];
    sh[threadIdx.x] = s; __syncthreads();
    for (int o = 128; o > 0; o >>= 1) {
        if (threadIdx.x < o) sh[threadIdx.x] += sh[threadIdx.x + o];
        __syncthreads();
    }
    if (threadIdx.x == 0) g_wpart[blockIdx.y * 64 + blockIdx.x] = sh[0];
}

// ---------------- finalize x stats + weight scales ----------------
__global__ void k_fin1() {
    int t = threadIdx.x;
    if (t < BATCH) {
        double s = 0.0, q = 0.0;
        for (int i = 0; i < 64; i++) { s += g_xpart_s[t*64+i]; q += g_xpart_q[t*64+i]; }
        double n = (double)BELEMS;
        double mu = s / n;
        double var = q / n - mu * mu;
        g_xmu[t]   = (float)mu;
        g_xrstd[t] = (float)(1.0 / sqrt(var + 1e-5));
    }
    if (t >= 8 && t < 13) {
        int wi = t - 8;
        double s = 0.0;
        for (int i = 0; i < 64; i++) s += g_wpart[wi*64+i];
        float m = (float)(s / (double)(DIM * DIM));
        if (m < 1e-5f) m = 1e-5f;
        float sc = 1.0f / m;        // ref: scale = 1/clip(mean,1e-5)
        g_wsc[wi]  = sc;
        g_wdeq[wi] = 1.0f / sc;     // ref: wq = t / scale
    }
}

// ---------------- ternarize weights -> bf16 {-1,0,1} ----------------
__global__ void k_tern(const float* a, const float* b2, const float* c,
                       const float* d, const float* e) {
    const float* ws[5] = {a, b2, c, d, e};
    int wi = blockIdx.y;
    const float* w = ws[wi];
    float sc = g_wsc[wi];
    __nv_bfloat16* out = g_Wt + (size_t)wi * DIM * DIM;
    for (int i = blockIdx.x * blockDim.x + threadIdx.x; i < DIM * DIM / 4;
         i += gridDim.x * blockDim.x) {
        float4 v = *(const float4*)(w + i * 4);
        float t0 = fminf(fmaxf(rintf(v.x * sc), -1.0f), 1.0f);
        float t1 = fminf(fmaxf(rintf(v.y * sc), -1.0f), 1.0f);
        float t2 = fminf(fmaxf(rintf(v.z * sc), -1.0f), 1.0f);
        float t3 = fminf(fmaxf(rintf(v.w * sc), -1.0f), 1.0f);
        __nv_bfloat162* o2 = (__nv_bfloat162*)(out + i * 4);
        o2[0] = __floats2bfloat162_rn(t0, t1);
        o2[1] = __floats2bfloat162_rn(t2, t3);
    }
}

// ---------------- per-row activation quant -> int-valued bf16 + row scale ----------------
__global__ void k_qact(const float* __restrict__ xin, int sel) {
    int row = blockIdx.x;
    int b = row >> 11;
    float mu = sel ? g_zmu[b]   : g_xmu[b];
    float rs = sel ? g_zrstd[b] : g_xrstd[b];
    const float* p = (sel ? (const float*)g_Z : xin) + (size_t)row * DIM;
    __nv_bfloat16* op = (sel ? g_A2q : g_Aq) + (size_t)row * DIM;

    int c0 = threadIdx.x * 4;
    float4 vv = *(const float4*)(p + c0);
    float v0 = (vv.x - mu) * rs, v1 = (vv.y - mu) * rs;
    float v2 = (vv.z - mu) * rs, v3 = (vv.w - mu) * rs;
    float mx = fmaxf(fmaxf(fabsf(v0), fabsf(v1)), fmaxf(fabsf(v2), fabsf(v3)));

    __shared__ float sh[256];
    sh[threadIdx.x] = mx; __syncthreads();
    for (int o = 128; o > 0; o >>= 1) {
        if (threadIdx.x < o) sh[threadIdx.x] = fmaxf(sh[threadIdx.x], sh[threadIdx.x + o]);
        __syncthreads();
    }
    float maxc  = fmaxf(sh[0], 1e-5f);
    float scale = 127.0f / maxc;

    float q0 = fminf(fmaxf(rintf(v0 * scale), -128.0f), 127.0f);
    float q1 = fminf(fmaxf(rintf(v1 * scale), -128.0f), 127.0f);
    float q2 = fminf(fmaxf(rintf(v2 * scale), -128.0f), 127.0f);
    float q3 = fminf(fmaxf(rintf(v3 * scale), -128.0f), 127.0f);
    __nv_bfloat162* o2 = (__nv_bfloat162*)(op + c0);
    o2[0] = __floats2bfloat162_rn(q0, q1);
    o2[1] = __floats2bfloat162_rn(q2, q3);

    if (threadIdx.x == 0) {
        float* rp = sel ? g_a2row : g_arow;
        rp[row] = 1.0f / scale;                 // ref: y = q / scale
    }
}

// ---------------- decay table ----------------
__global__ void k_decay() {
    int h = blockIdx.x;
    double a = log(1.0 / 32.0), bq = log(1.0 / 512.0);
    double lin = a + (bq - a) * ((double)h / 15.0);
    double gamma = 1.0 - exp(lin);
    double lg = log(gamma);
    for (int d = threadIdx.x; d < NSEQ; d += blockDim.x)
        g_decay[h * NSEQ + d] = (float)exp(lg * (double)d);
}

// ---------------- bf16 tensor-core GEMM (exact integer arithmetic) ----------------
__device__ __forceinline__ void ldmx4(uint32_t& r0, uint32_t& r1,
                                      uint32_t& r2, uint32_t& r3, uint32_t addr) {
    asm volatile("ldmatrix.sync.aligned.m8n8.x4.shared.b16 {%0,%1,%2,%3}, [%4];"
        : "=r"(r0), "=r"(r1), "=r"(r2), "=r"(r3) : "r"(addr));
}
__device__ __forceinline__ void mma16816(float* c, const uint32_t* a,
                                         uint32_t b0, uint32_t b1) {
    asm volatile("mma.sync.aligned.m16n8k16.row.col.f32.bf16.bf16.f32 "
        "{%0,%1,%2,%3},{%4,%5,%6,%7},{%8,%9},{%0,%1,%2,%3};"
        : "+f"(c[0]), "+f"(c[1]), "+f"(c[2]), "+f"(c[3])
        : "r"(a[0]), "r"(a[1]), "r"(a[2]), "r"(a[3]), "r"(b0), "r"(b1));
}

#define SPITCH 40   // bf16 pitch: 80B rows -> conflict-free ldmatrix

__global__ void __launch_bounds__(256) k_gemm_mma(int baseMode, float* __restrict__ dst) {
    int mode = baseMode + blockIdx.z;
    const __nv_bfloat16* A = (mode == 4) ? g_A2q : g_Aq;
    const float* arow      = (mode == 4) ? g_a2row : g_arow;
    const __nv_bfloat16* W = g_Wt + (size_t)mode * DIM * DIM;
    float wsc = g_wdeq[mode];

    __shared__ __nv_bfloat16 As[128 * SPITCH];
    __shared__ __nv_bfloat16 Bs[128 * SPITCH];

    int tid = threadIdx.x;
    int warp = tid >> 5, lane = tid & 31;
    int wm = warp >> 2, wn = warp & 3;           // 2 x 4 warp grid

    const __nv_bfloat16* Ag = A + (size_t)blockIdx.y * 128 * DIM;
    const __nv_bfloat16* Wg = W + (size_t)blockIdx.x * 128 * DIM;

    int lr0 = tid >> 2;                          // 0..63
    int lc0 = (tid & 3) * 8;                     // 0,8,16,24

    uint32_t sA = (uint32_t)__cvta_generic_to_shared(&As[0]);
    uint32_t sB = (uint32_t)__cvta_generic_to_shared(&Bs[0]);

    int a_row = wm * 64 + (lane & 15);
    int a_col = ((lane >> 4) << 3);
    int b_row = wn * 32 + (lane & 7) + (((lane >> 4) & 1) << 3);
    int b_col = (((lane >> 3) & 1) << 3);

    float c[4][4][4];
    #pragma unroll
    for (int mi = 0; mi < 4; mi++)
        #pragma unroll
        for (int ni = 0; ni < 4; ni++)
            #pragma unroll
            for (int r = 0; r < 4; r++) c[mi][ni][r] = 0.0f;

    // prefetch tile 0
    uint4 ra0 = *(const uint4*)(Ag + (size_t)lr0        * DIM + lc0);
    uint4 ra1 = *(const uint4*)(Ag + (size_t)(lr0 + 64) * DIM + lc0);
    uint4 rb0 = *(const uint4*)(Wg + (size_t)lr0        * DIM + lc0);
    uint4 rb1 = *(const uint4*)(Wg + (size_t)(lr0 + 64) * DIM + lc0);

    for (int kt = 0; kt < 32; ++kt) {
        __syncthreads();
        *(uint4*)&As[lr0 * SPITCH + lc0]        = ra0;
        *(uint4*)&As[(lr0 + 64) * SPITCH + lc0] = ra1;
        *(uint4*)&Bs[lr0 * SPITCH + lc0]        = rb0;
        *(uint4*)&Bs[(lr0 + 64) * SPITCH + lc0] = rb1;
        __syncthreads();

        if (kt < 31) {
            int kc = (kt + 1) * 32 + lc0;
            ra0 = *(const uint4*)(Ag + (size_t)lr0        * DIM + kc);
            ra1 = *(const uint4*)(Ag + (size_t)(lr0 + 64) * DIM + kc);
            rb0 = *(const uint4*)(Wg + (size_t)lr0        * DIM + kc);
            rb1 = *(const uint4*)(Wg + (size_t)(lr0 + 64) * DIM + kc);
        }

        #pragma unroll
        for (int kk = 0; kk < 2; ++kk) {
            uint32_t afr[4][4], bfr[2][4];
            #pragma unroll
            for (int mi = 0; mi < 4; mi++) {
                uint32_t smaddr = sA + (uint32_t)((a_row + mi * 16) * SPITCH + kk * 16 + a_col) * 2u;
                ldmx4(afr[mi][0], afr[mi][1], afr[mi][2], afr[mi][3], smaddr);
            }
            #pragma unroll
            for (int p = 0; p < 2; p++) {
                uint32_t smaddr = sB + (uint32_t)((b_row + p * 16) * SPITCH + kk * 16 + b_col) * 2u;
                ldmx4(bfr[p][0], bfr[p][1], bfr[p][2], bfr[p][3], smaddr);
            }
            #pragma unroll
            for (int mi = 0; mi < 4; mi++)
                #pragma unroll
                for (int ni = 0; ni < 4; ni++)
                    mma16816(c[mi][ni], afr[mi],
                             bfr[ni >> 1][(ni & 1) * 2], bfr[ni >> 1][(ni & 1) * 2 + 1]);
        }
    }

    // epilogue
    int m_base = blockIdx.y * 128 + wm * 64;
    int n_base = blockIdx.x * 128 + wn * 32;
    int lr = lane >> 2;
    int lc = (lane & 3) * 2;

    #pragma unroll
    for (int mi = 0; mi < 4; mi++) {
        #pragma unroll
        for (int rr = 0; rr < 2; rr++) {
            int m = m_base + mi * 16 + rr * 8 + lr;
            float sc = arow[m] * wsc;
            if (mode <= 2) {
                float* dp = (mode == 0) ? g_Q : (mode == 1) ? g_K : g_V;
                int bb = m >> 11, ns = m & 2047;
                #pragma unroll
                for (int ni = 0; ni < 4; ni++) {
                    int n = n_base + ni * 8 + lc;
                    int hh = n >> 6, dd = n & 63;
                    float2 o;
                    o.x = c[mi][ni][rr * 2 + 0] * sc;
                    o.y = c[mi][ni][rr * 2 + 1] * sc;
                    *(float2*)&dp[(((size_t)(bb * NH + hh)) * NSEQ + ns) * HD + dd] = o;
                }
            } else if (mode == 3) {
                #pragma unroll
                for (int ni = 0; ni < 4; ni++) {
                    int n = n_base + ni * 8 + lc;
                    float v0 = c[mi][ni][rr * 2 + 0] * sc;
                    float v1 = c[mi][ni][rr * 2 + 1] * sc;
                    float2 o;
                    o.x = v0 / (1.0f + expf(-v0));
                    o.y = v1 / (1.0f + expf(-v1));
                    *(float2*)&g_G[(size_t)m * DIM + n] = o;
                }
            } else {
                #pragma unroll
                for (int ni = 0; ni < 4; ni++) {
                    int n = n_base + ni * 8 + lc;
                    float2 o;
                    o.x = c[mi][ni][rr * 2 + 0] * sc;
                    o.y = c[mi][ni][rr * 2 + 1] * sc;
                    *(float2*)&dst[(size_t)m * DIM + n] = o;
                }
            }
        }
    }
}

// ---------------- retention attention (fp32, vectorized smem) ----------------
#define AP 68   // float pitch: 272B rows, 16B aligned
__global__ void __launch_bounds__(256) k_attn() {
    int nt = blockIdx.x, h = blockIdx.y, b = blockIdx.z;
    int n0 = nt * 64;
    size_t base = ((size_t)(b * NH + h)) * NSEQ * HD;
    const float* Qp = g_Q + base;
    const float* Kp = g_K + base;
    const float* Vp = g_V + base;
    const float* dec = g_decay + (size_t)h * NSEQ;

    __shared__ float Qs[64 * AP];   // transposed: [dd][r]
    __shared__ float KS[64 * AP];   // K transposed [dd][m], later S as [m][r]
    __shared__ float Vs[32 * AP];   // natural [m][dd], half tile

    int tid = threadIdx.x;
    int ty = tid >> 4, tx = tid & 15;
    int r0 = ty * 4, c0 = tx * 4;

    for (int i4 = tid; i4 < 1024; i4 += 256) {
        int r = i4 >> 4;
        int d0 = (i4 & 15) << 2;
        float4 qv = *(const float4*)(Qp + (size_t)(n0 + r) * HD + d0);
        Qs[(d0+0)*AP + r] = qv.x; Qs[(d0+1)*AP + r] = qv.y;
        Qs[(d0+2)*AP + r] = qv.z; Qs[(d0+3)*AP + r] = qv.w;
    }

    float yacc[4][4];
    #pragma unroll
    for (int i = 0; i < 4; i++)
        #pragma unroll
        for (int j = 0; j < 4; j++) yacc[i][j] = 0.0f;

    for (int mt = 0; mt <= nt; ++mt) {
        int m0 = mt * 64;
        __syncthreads();
        for (int i4 = tid; i4 < 1024; i4 += 256) {
            int r = i4 >> 4;
            int d0 = (i4 & 15) << 2;
            float4 kv = *(const float4*)(Kp + (size_t)(m0 + r) * HD + d0);
            KS[(d0+0)*AP + r] = kv.x; KS[(d0+1)*AP + r] = kv.y;
            KS[(d0+2)*AP + r] = kv.z; KS[(d0+3)*AP + r] = kv.w;
        }
        __syncthreads();

        float s[4][4];
        #pragma unroll
        for (int i = 0; i < 4; i++)
            #pragma unroll
            for (int j = 0; j < 4; j++) s[i][j] = 0.0f;

        #pragma unroll 8
        for (int kk = 0; kk < 64; ++kk) {
            float4 q4 = *(const float4*)&Qs[kk*AP + r0];
            float4 k4 = *(const float4*)&KS[kk*AP + c0];
            s[0][0]+=q4.x*k4.x; s[0][1]+=q4.x*k4.y; s[0][2]+=q4.x*k4.z; s[0][3]+=q4.x*k4.w;
            s[1][0]+=q4.y*k4.x; s[1][1]+=q4.y*k4.y; s[1][2]+=q4.y*k4.z; s[1][3]+=q4.y*k4.w;
            s[2][0]+=q4.z*k4.x; s[2][1]+=q4.z*k4.y; s[2][2]+=q4.z*k4.z; s[2][3]+=q4.z*k4.w;
            s[3][0]+=q4.w*k4.x; s[3][1]+=q4.w*k4.y; s[3][2]+=q4.w*k4.z; s[3][3]+=q4.w*k4.w;
        }
        __syncthreads();

        // decay + causal, store S transposed [m][r] over KS (float4 along r)
        #pragma unroll
        for (int j = 0; j < 4; j++) {
            float4 col;
            float* cp = (float*)&col;
            #pragma unroll
            for (int i = 0; i < 4; i++) {
                int d = (n0 + r0 + i) - (m0 + c0 + j);
                cp[i] = (d >= 0) ? s[i][j] * 0.125f * dec[d] : 0.0f;
            }
            *(float4*)&KS[(c0 + j)*AP + r0] = col;
        }
        __syncthreads();

        #pragma unroll
        for (int half = 0; half < 2; ++half) {
            int mb = half * 32;
            for (int i4 = tid; i4 < 512; i4 += 256) {
                int r = i4 >> 4;
                int d0 = (i4 & 15) << 2;
                float4 vv = *(const float4*)(Vp + (size_t)(m0 + mb + r) * HD + d0);
                *(float4*)&Vs[r*AP + d0] = vv;
            }
            __syncthreads();
            #pragma unroll 8
            for (int mm = 0; mm < 32; ++mm) {
                float4 s4 = *(const float4*)&KS[(mb + mm)*AP + r0];
                float4 v4 = *(const float4*)&Vs[mm*AP + c0];
                yacc[0][0]+=s4.x*v4.x; yacc[0][1]+=s4.x*v4.y; yacc[0][2]+=s4.x*v4.z; yacc[0][3]+=s4.x*v4.w;
                yacc[1][0]+=s4.y*v4.x; yacc[1][1]+=s4.y*v4.y; yacc[1][2]+=s4.y*v4.z; yacc[1][3]+=s4.y*v4.w;
                yacc[2][0]+=s4.z*v4.x; yacc[2][1]+=s4.z*v4.y; yacc[2][2]+=s4.z*v4.z; yacc[2][3]+=s4.z*v4.w;
                yacc[3][0]+=s4.w*v4.x; yacc[3][1]+=s4.w*v4.y; yacc[3][2]+=s4.w*v4.z; yacc[3][3]+=s4.w*v4.w;
            }
            __syncthreads();
        }
    }

    #pragma unroll
    for (int i = 0; i < 4; i++) {
        float4 o; o.x=yacc[i][0]; o.y=yacc[i][1]; o.z=yacc[i][2]; o.w=yacc[i][3];
        *(float4*)&g_Y[(size_t)(b*NSEQ + n0 + r0 + i)*DIM + h*HD + c0] = o;
    }
}

// ---------------- LN(y)*silu(g) + per-row double partials ----------------
__global__ void k_lng(const float* __restrict__ lnw, const float* __restrict__ lnb) {
    int row = blockIdx.x;
    const float* y = g_Y + (size_t)row * DIM;
    int c0 = threadIdx.x * 4;
    float4 yv = *(const float4*)(y + c0);

    __shared__ double shs[256], shq[256];
    shs[threadIdx.x] = (double)yv.x + yv.y + yv.z + yv.w;
    shq[threadIdx.x] = (double)yv.x*yv.x + (double)yv.y*yv.y
                     + (double)yv.z*yv.z + (double)yv.w*yv.w;
    __syncthreads();
    for (int o = 128; o > 0; o >>= 1) {
        if (threadIdx.x < o) {
            shs[threadIdx.x] += shs[threadIdx.x + o];
            shq[threadIdx.x] += shq[threadIdx.x + o];
        }
        __syncthreads();
    }
    double mu_d  = shs[0] / (double)DIM;
    double var_d = shq[0] / (double)DIM - mu_d * mu_d;
    float mu = (float)mu_d;
    float rs = (float)(1.0 / sqrt(var_d + 1e-5));
    __syncthreads();

    float4 g4 = *(const float4*)(g_G + (size_t)row * DIM + c0);
    float4 w4 = *(const float4*)(lnw + c0);
    float4 b4 = *(const float4*)(lnb + c0);
    float4 z;
    z.x = ((yv.x - mu) * rs * w4.x + b4.x) * g4.x;
    z.y = ((yv.y - mu) * rs * w4.y + b4.y) * g4.y;
    z.z = ((yv.z - mu) * rs * w4.z + b4.z) * g4.z;
    z.w = ((yv.w - mu) * rs * w4.w + b4.w) * g4.w;
    *(float4*)(g_Z + (size_t)row * DIM + c0) = z;

    shs[threadIdx.x] = (double)z.x + z.y + z.z + z.w;
    shq[threadIdx.x] = (double)z.x*z.x + (double)z.y*z.y
                     + (double)z.z*z.z + (double)z.w*z.w;
    __syncthreads();
    for (int o = 128; o > 0; o >>= 1) {
        if (threadIdx.x < o) {
            shs[threadIdx.x] += shs[threadIdx.x + o];
            shq[threadIdx.x] += shq[threadIdx.x + o];
        }
        __syncthreads();
    }
    if (threadIdx.x == 0) {
        g_zpart_s[row] = shs[0];
        g_zpart_q[row] = shq[0];
    }
}

// ---------------- finalize z batch stats ----------------
__global__ void k_fin2() {
    int b = blockIdx.x;
    double s = 0.0, q = 0.0;
    for (int i = threadIdx.x; i < NSEQ; i += 256) {
        s += g_zpart_s[b * NSEQ + i];
        q += g_zpart_q[b * NSEQ + i];
    }
    __shared__ double shs[256], shq[256];
    shs[threadIdx.x] = s; shq[threadIdx.x] = q; __syncthreads();
    for (int o = 128; o > 0; o >>= 1) {
        if (threadIdx.x < o) {
            shs[threadIdx.x] += shs[threadIdx.x + o];
            shq[threadIdx.x] += shq[threadIdx.x + o];
        }
        __syncthreads();
    }
    if (threadIdx.x == 0) {
        double n = (double)BELEMS;
        double mu = shs[0] / n;
        double var = shq[0] / n - mu * mu;
        g_zmu[b]   = (float)mu;
        g_zrstd[b] = (float)(1.0 / sqrt(var + 1e-5));
    }
}

// ---------------- launch ----------------
extern "C" void kernel_launch(void* const* d_in, const int* in_sizes, int n_in,
                              void* d_out, int out_size) {
    (void)in_sizes; (void)n_in; (void)out_size;
    const float* x   = (const float*)d_in[0];
    const float* wq  = (const float*)d_in[1];
    const float* wk  = (const float*)d_in[2];
    const float* wv  = (const float*)d_in[3];
    const float* wg  = (const float*)d_in[4];
    const float* wo  = (const float*)d_in[5];
    const float* lnw = (const float*)d_in[6];
    const float* lnb = (const float*)d_in[7];
    float* out = (float*)d_out;

    k_reduce_x   <<<dim3(64, BATCH), 256>>>(x);
    k_reduce_wabs<<<dim3(64, 5),     256>>>(wq, wk, wv, wg, wo);
    k_fin1       <<<1, 32>>>();
    k_tern       <<<dim3(256, 5),    256>>>(wq, wk, wv, wg, wo);
    k_qact       <<<ROWS, 256>>>(x, 0);
    k_decay      <<<NH, 256>>>();
    k_gemm_mma   <<<dim3(8, 32, 4),  256>>>(0, out);   // Q,K,V,G
    k_attn       <<<dim3(NSEQ/64, NH, BATCH), 256>>>();
    k_lng        <<<ROWS, 256>>>(lnw, lnb);
    k_fin2       <<<BATCH, 256>>>();
    k_qact       <<<ROWS, 256>>>(x, 1);                // quantize z
    k_gemm_mma   <<<dim3(8, 32, 1),  256>>>(4, out);   // final projection
}

// round 8
// speedup vs baseline: 2.7566x; 1.5217x over previous
#include <cuda_runtime.h>
#include <cuda_bf16.h>
#include <cstdint>
#include <stdint.h>
#include <math.h>

#define BATCH 2
#define NSEQ 2048
#define DIM 1024
#define NH 16
#define HD 64
#define ROWS (BATCH*NSEQ)          // 4096
#define BELEMS (NSEQ*DIM)          // 2097152

// ---------------- device scratch ----------------
__device__ double g_xpart_s[BATCH*64], g_xpart_q[BATCH*64];
__device__ double g_wpart[5*64];
__device__ double g_zpart_s[ROWS], g_zpart_q[ROWS];
__device__ float  g_xmu[BATCH], g_xrstd[BATCH];
__device__ float  g_zmu[BATCH], g_zrstd[BATCH];
__device__ float  g_wsc[5];
__device__ float  g_wdeq[5];
__device__ __nv_bfloat16 g_Aq [ROWS*DIM];
__device__ __nv_bfloat16 g_A2q[ROWS*DIM];
__device__ float  g_arow [ROWS];
__device__ float  g_a2row[ROWS];
__device__ __nv_bfloat16 g_Wt[5*DIM*DIM];
// Q/K/V in bf16 hi/lo pairs, layout [B,H,N,HD]; Q pre-scaled by 0.125
__device__ __nv_bfloat16 g_Qh[BATCH*NH*NSEQ*HD], g_Ql[BATCH*NH*NSEQ*HD];
__device__ __nv_bfloat16 g_Kh[BATCH*NH*NSEQ*HD], g_Kl[BATCH*NH*NSEQ*HD];
__device__ __nv_bfloat16 g_Vh[BATCH*NH*NSEQ*HD], g_Vl[BATCH*NH*NSEQ*HD];
__device__ float  g_G [ROWS*DIM];
__device__ float  g_Y [ROWS*DIM];
__device__ float  g_Z [ROWS*DIM];
__device__ float  g_decay[NH*NSEQ];

// ---------------- batch stats of x ----------------
__global__ void k_reduce_x(const float* __restrict__ x) {
    int b = blockIdx.y;
    const float* p = x + (size_t)b * BELEMS;
    double s = 0.0, q = 0.0;
    for (int i = blockIdx.x * blockDim.x + threadIdx.x; i < BELEMS;
         i += gridDim.x * blockDim.x) {
        double v = (double)p[i];
        s += v; q += v * v;
    }
    __shared__ double shs[256], shq[256];
    shs[threadIdx.x] = s; shq[threadIdx.x] = q; __syncthreads();
    for (int o = 128; o > 0; o >>= 1) {
        if (threadIdx.x < o) {
            shs[threadIdx.x] += shs[threadIdx.x + o];
            shq[threadIdx.x] += shq[threadIdx.x + o];
        }
        __syncthreads();
    }
    if (threadIdx.x == 0) {
        g_xpart_s[b * 64 + blockIdx.x] = shs[0];
        g_xpart_q[b * 64 + blockIdx.x] = shq[0];
    }
}

__global__ void k_reduce_wabs(const float* a, const float* b2, const float* c,
                              const float* d, const float* e) {
    const float* ws[5] = {a, b2, c, d, e};
    const float* w = ws[blockIdx.y];
    double s = 0.0;
    for (int i = blockIdx.x * blockDim.x + threadIdx.x; i < DIM * DIM;
         i += gridDim.x * blockDim.x)
        s += (double)fabsf(w[i]);
    __shared__ double sh[256];
    sh[threadIdx.x] = s; __syncthreads();
    for (int o = 128; o > 0; o >>= 1) {
        if (threadIdx.x < o) sh[threadIdx.x] += sh[threadIdx.x + o];
        __syncthreads();
    }
    if (threadIdx.x == 0) g_wpart[blockIdx.y * 64 + blockIdx.x] = sh[0];
}

__global__ void k_fin1() {
    int t = threadIdx.x;
    if (t < BATCH) {
        double s = 0.0, q = 0.0;
        for (int i = 0; i < 64; i++) { s += g_xpart_s[t*64+i]; q += g_xpart_q[t*64+i]; }
        double n = (double)BELEMS;
        double mu = s / n;
        double var = q / n - mu * mu;
        g_xmu[t]   = (float)mu;
        g_xrstd[t] = (float)(1.0 / sqrt(var + 1e-5));
    }
    if (t >= 8 && t < 13) {
        int wi = t - 8;
        double s = 0.0;
        for (int i = 0; i < 64; i++) s += g_wpart[wi*64+i];
        float m = (float)(s / (double)(DIM * DIM));
        if (m < 1e-5f) m = 1e-5f;
        float sc = 1.0f / m;
        g_wsc[wi]  = sc;
        g_wdeq[wi] = 1.0f / sc;
    }
}

__global__ void k_tern(const float* a, const float* b2, const float* c,
                       const float* d, const float* e) {
    const float* ws[5] = {a, b2, c, d, e};
    int wi = blockIdx.y;
    const float* w = ws[wi];
    float sc = g_wsc[wi];
    __nv_bfloat16* out = g_Wt + (size_t)wi * DIM * DIM;
    for (int i = blockIdx.x * blockDim.x + threadIdx.x; i < DIM * DIM / 4;
         i += gridDim.x * blockDim.x) {
        float4 v = *(const float4*)(w + i * 4);
        float t0 = fminf(fmaxf(rintf(v.x * sc), -1.0f), 1.0f);
        float t1 = fminf(fmaxf(rintf(v.y * sc), -1.0f), 1.0f);
        float t2 = fminf(fmaxf(rintf(v.z * sc), -1.0f), 1.0f);
        float t3 = fminf(fmaxf(rintf(v.w * sc), -1.0f), 1.0f);
        __nv_bfloat162* o2 = (__nv_bfloat162*)(out + i * 4);
        o2[0] = __floats2bfloat162_rn(t0, t1);
        o2[1] = __floats2bfloat162_rn(t2, t3);
    }
}

__global__ void k_qact(const float* __restrict__ xin, int sel) {
    int row = blockIdx.x;
    int b = row >> 11;
    float mu = sel ? g_zmu[b]   : g_xmu[b];
    float rs = sel ? g_zrstd[b] : g_xrstd[b];
    const float* p = (sel ? (const float*)g_Z : xin) + (size_t)row * DIM;
    __nv_bfloat16* op = (sel ? g_A2q : g_Aq) + (size_t)row * DIM;

    int c0 = threadIdx.x * 4;
    float4 vv = *(const float4*)(p + c0);
    float v0 = (vv.x - mu) * rs, v1 = (vv.y - mu) * rs;
    float v2 = (vv.z - mu) * rs, v3 = (vv.w - mu) * rs;
    float mx = fmaxf(fmaxf(fabsf(v0), fabsf(v1)), fmaxf(fabsf(v2), fabsf(v3)));

    __shared__ float sh[256];
    sh[threadIdx.x] = mx; __syncthreads();
    for (int o = 128; o > 0; o >>= 1) {
        if (threadIdx.x < o) sh[threadIdx.x] = fmaxf(sh[threadIdx.x], sh[threadIdx.x + o]);
        __syncthreads();
    }
    float maxc  = fmaxf(sh[0], 1e-5f);
    float scale = 127.0f / maxc;

    float q0 = fminf(fmaxf(rintf(v0 * scale), -128.0f), 127.0f);
    float q1 = fminf(fmaxf(rintf(v1 * scale), -128.0f), 127.0f);
    float q2 = fminf(fmaxf(rintf(v2 * scale), -128.0f), 127.0f);
    float q3 = fminf(fmaxf(rintf(v3 * scale), -128.0f), 127.0f);
    __nv_bfloat162* o2 = (__nv_bfloat162*)(op + c0);
    o2[0] = __floats2bfloat162_rn(q0, q1);
    o2[1] = __floats2bfloat162_rn(q2, q3);

    if (threadIdx.x == 0) {
        float* rp = sel ? g_a2row : g_arow;
        rp[row] = 1.0f / scale;
    }
}

__global__ void k_decay() {
    int h = blockIdx.x;
    double a = log(1.0 / 32.0), bq = log(1.0 / 512.0);
    double lin = a + (bq - a) * ((double)h / 15.0);
    double gamma = 1.0 - exp(lin);
    double lg = log(gamma);
    for (int d = threadIdx.x; d < NSEQ; d += blockDim.x)
        g_decay[h * NSEQ + d] = (float)exp(lg * (double)d);
}

// ---------------- mma helpers ----------------
__device__ __forceinline__ void ldmx4(uint32_t& r0, uint32_t& r1,
                                      uint32_t& r2, uint32_t& r3, uint32_t addr) {
    asm volatile("ldmatrix.sync.aligned.m8n8.x4.shared.b16 {%0,%1,%2,%3}, [%4];"
        : "=r"(r0), "=r"(r1), "=r"(r2), "=r"(r3) : "r"(addr));
}
__device__ __forceinline__ void ldmx4t(uint32_t& r0, uint32_t& r1,
                                       uint32_t& r2, uint32_t& r3, uint32_t addr) {
    asm volatile("ldmatrix.sync.aligned.m8n8.x4.trans.shared.b16 {%0,%1,%2,%3}, [%4];"
        : "=r"(r0), "=r"(r1), "=r"(r2), "=r"(r3) : "r"(addr));
}
__device__ __forceinline__ void mma16816(float* c, const uint32_t* a,
                                         uint32_t b0, uint32_t b1) {
    asm volatile("mma.sync.aligned.m16n8k16.row.col.f32.bf16.bf16.f32 "
        "{%0,%1,%2,%3},{%4,%5,%6,%7},{%8,%9},{%0,%1,%2,%3};"
        : "+f"(c[0]), "+f"(c[1]), "+f"(c[2]), "+f"(c[3])
        : "r"(a[0]), "r"(a[1]), "r"(a[2]), "r"(a[3]), "r"(b0), "r"(b1));
}

#define SPITCH 40

__global__ void __launch_bounds__(256) k_gemm_mma(int baseMode, float* __restrict__ dst) {
    int mode = baseMode + blockIdx.z;
    const __nv_bfloat16* A = (mode == 4) ? g_A2q : g_Aq;
    const float* arow      = (mode == 4) ? g_a2row : g_arow;
    const __nv_bfloat16* W = g_Wt + (size_t)mode * DIM * DIM;
    float wsc = g_wdeq[mode];

    __shared__ __nv_bfloat16 As[128 * SPITCH];
    __shared__ __nv_bfloat16 Bs[128 * SPITCH];

    int tid = threadIdx.x;
    int warp = tid >> 5, lane = tid & 31;
    int wm = warp >> 2, wn = warp & 3;

    const __nv_bfloat16* Ag = A + (size_t)blockIdx.y * 128 * DIM;
    const __nv_bfloat16* Wg = W + (size_t)blockIdx.x * 128 * DIM;

    int lr0 = tid >> 2;
    int lc0 = (tid & 3) * 8;

    uint32_t sA = (uint32_t)__cvta_generic_to_shared(&As[0]);
    uint32_t sB = (uint32_t)__cvta_generic_to_shared(&Bs[0]);

    int a_row = wm * 64 + (lane & 15);
    int a_col = ((lane >> 4) << 3);
    int b_row = wn * 32 + (lane & 7) + (((lane >> 4) & 1) << 3);
    int b_col = (((lane >> 3) & 1) << 3);

    float c[4][4][4];
    #pragma unroll
    for (int mi = 0; mi < 4; mi++)
        #pragma unroll
        for (int ni = 0; ni < 4; ni++)
            #pragma unroll
            for (int r = 0; r < 4; r++) c[mi][ni][r] = 0.0f;

    uint4 ra0 = *(const uint4*)(Ag + (size_t)lr0        * DIM + lc0);
    uint4 ra1 = *(const uint4*)(Ag + (size_t)(lr0 + 64) * DIM + lc0);
    uint4 rb0 = *(const uint4*)(Wg + (size_t)lr0        * DIM + lc0);
    uint4 rb1 = *(const uint4*)(Wg + (size_t)(lr0 + 64) * DIM + lc0);

    for (int kt = 0; kt < 32; ++kt) {
        __syncthreads();
        *(uint4*)&As[lr0 * SPITCH + lc0]        = ra0;
        *(uint4*)&As[(lr0 + 64) * SPITCH + lc0] = ra1;
        *(uint4*)&Bs[lr0 * SPITCH + lc0]        = rb0;
        *(uint4*)&Bs[(lr0 + 64) * SPITCH + lc0] = rb1;
        __syncthreads();

        if (kt < 31) {
            int kc = (kt + 1) * 32 + lc0;
            ra0 = *(const uint4*)(Ag + (size_t)lr0        * DIM + kc);
            ra1 = *(const uint4*)(Ag + (size_t)(lr0 + 64) * DIM + kc);
            rb0 = *(const uint4*)(Wg + (size_t)lr0        * DIM + kc);
            rb1 = *(const uint4*)(Wg + (size_t)(lr0 + 64) * DIM + kc);
        }

        #pragma unroll
        for (int kk = 0; kk < 2; ++kk) {
            uint32_t afr[4][4], bfr[2][4];
            #pragma unroll
            for (int mi = 0; mi < 4; mi++) {
                uint32_t smaddr = sA + (uint32_t)((a_row + mi * 16) * SPITCH + kk * 16 + a_col) * 2u;
                ldmx4(afr[mi][0], afr[mi][1], afr[mi][2], afr[mi][3], smaddr);
            }
            #pragma unroll
            for (int p = 0; p < 2; p++) {
                uint32_t smaddr = sB + (uint32_t)((b_row + p * 16) * SPITCH + kk * 16 + b_col) * 2u;
                ldmx4(bfr[p][0], bfr[p][1], bfr[p][2], bfr[p][3], smaddr);
            }
            #pragma unroll
            for (int mi = 0; mi < 4; mi++)
                #pragma unroll
                for (int ni = 0; ni < 4; ni++)
                    mma16816(c[mi][ni], afr[mi],
                             bfr[ni >> 1][(ni & 1) * 2], bfr[ni >> 1][(ni & 1) * 2 + 1]);
        }
    }

    int m_base = blockIdx.y * 128 + wm * 64;
    int n_base = blockIdx.x * 128 + wn * 32;
    int lr = lane >> 2;
    int lc = (lane & 3) * 2;

    #pragma unroll
    for (int mi = 0; mi < 4; mi++) {
        #pragma unroll
        for (int rr = 0; rr < 2; rr++) {
            int m = m_base + mi * 16 + rr * 8 + lr;
            float sc = arow[m] * wsc;
            if (mode <= 2) {
                __nv_bfloat16* hp = (mode == 0) ? g_Qh : (mode == 1) ? g_Kh : g_Vh;
                __nv_bfloat16* lp = (mode == 0) ? g_Ql : (mode == 1) ? g_Kl : g_Vl;
                float sce = (mode == 0) ? sc * 0.125f : sc;
                int bb = m >> 11, ns = m & 2047;
                #pragma unroll
                for (int ni = 0; ni < 4; ni++) {
                    int n = n_base + ni * 8 + lc;
                    int hh = n >> 6, dd = n & 63;
                    float v0 = c[mi][ni][rr * 2 + 0] * sce;
                    float v1 = c[mi][ni][rr * 2 + 1] * sce;
                    __nv_bfloat16 h0 = __float2bfloat16(v0);
                    __nv_bfloat16 h1 = __float2bfloat16(v1);
                    float l0 = v0 - __bfloat162float(h0);
                    float l1 = v1 - __bfloat162float(h1);
                    size_t idx = (((size_t)(bb * NH + hh)) * NSEQ + ns) * HD + dd;
                    __nv_bfloat162 hv; hv.x = h0; hv.y = h1;
                    __nv_bfloat162 lv; lv.x = __float2bfloat16(l0); lv.y = __float2bfloat16(l1);
                    *(__nv_bfloat162*)&hp[idx] = hv;
                    *(__nv_bfloat162*)&lp[idx] = lv;
                }
            } else if (mode == 3) {
                #pragma unroll
                for (int ni = 0; ni < 4; ni++) {
                    int n = n_base + ni * 8 + lc;
                    float v0 = c[mi][ni][rr * 2 + 0] * sc;
                    float v1 = c[mi][ni][rr * 2 + 1] * sc;
                    float2 o;
                    o.x = v0 / (1.0f + expf(-v0));
                    o.y = v1 / (1.0f + expf(-v1));
                    *(float2*)&g_G[(size_t)m * DIM + n] = o;
                }
            } else {
                #pragma unroll
                for (int ni = 0; ni < 4; ni++) {
                    int n = n_base + ni * 8 + lc;
                    float2 o;
                    o.x = c[mi][ni][rr * 2 + 0] * sc;
                    o.y = c[mi][ni][rr * 2 + 1] * sc;
                    *(float2*)&dst[(size_t)m * DIM + n] = o;
                }
            }
        }
    }
}

// ---------------- tensor-core retention attention (bf16 hi/lo x3) ----------------
#define BP 72   // bf16 pitch for 64-wide tiles (144B rows, conflict-free ldmatrix)
#define VP 40   // bf16 pitch for 32-wide V half tiles (80B rows)

__global__ void __launch_bounds__(256) k_attn_mma() {
    int nt = blockIdx.x, h = blockIdx.y, b = blockIdx.z;
    int n0 = nt * 64;
    size_t base = ((size_t)(b * NH + h)) * NSEQ * HD;
    const __nv_bfloat16 *Qhp = g_Qh + base, *Qlp = g_Ql + base;
    const __nv_bfloat16 *Khp = g_Kh + base, *Klp = g_Kl + base;
    const __nv_bfloat16 *Vhp = g_Vh + base, *Vlp = g_Vl + base;
    const float* dec = g_decay + (size_t)h * NSEQ;

    __shared__ __nv_bfloat16 sQh[64 * BP], sQl[64 * BP];
    __shared__ __nv_bfloat16 sKh[64 * BP], sKl[64 * BP];   // reused for S hi/lo
    __shared__ __nv_bfloat16 sVh[64 * VP], sVl[64 * VP];

    int tid = threadIdx.x;
    int warp = tid >> 5, lane = tid & 31;
    int wm = warp & 3, wn = warp >> 2;       // 4 (rows) x 2 (cols)

    uint32_t aQh = (uint32_t)__cvta_generic_to_shared(sQh);
    uint32_t aQl = (uint32_t)__cvta_generic_to_shared(sQl);
    uint32_t aKh = (uint32_t)__cvta_generic_to_shared(sKh);
    uint32_t aKl = (uint32_t)__cvta_generic_to_shared(sKl);
    uint32_t aVh = (uint32_t)__cvta_generic_to_shared(sVh);
    uint32_t aVl = (uint32_t)__cvta_generic_to_shared(sVl);

    // load Q tiles (64 rows x 64 cols bf16 = 512 16B chunks, x2 arrays)
    for (int j = tid; j < 512; j += 256) {
        int r = j >> 3, c8 = (j & 7) * 8;
        *(uint4*)&sQh[r * BP + c8] = *(const uint4*)(Qhp + (size_t)(n0 + r) * HD + c8);
        *(uint4*)&sQl[r * BP + c8] = *(const uint4*)(Qlp + (size_t)(n0 + r) * HD + c8);
    }

    // fragment addressing
    int a_row = wm * 16 + (lane & 15);
    int a_sel = (lane >> 4) << 3;
    int bq_row = wn * 32 + (lane & 7) + (((lane >> 4) & 1) << 3);
    int bq_col = ((lane >> 3) & 1) << 3;
    int bv_row = lane & 15;
    int bv_col = wn * 16 + (((lane >> 4) & 1) << 3);
    int lr = lane >> 2, lc2 = (lane & 3) * 2;

    float yacc[2][2][4];
    #pragma unroll
    for (int i = 0; i < 2; i++)
        #pragma unroll
        for (int j = 0; j < 2; j++)
            #pragma unroll
            for (int r = 0; r < 4; r++) yacc[i][j][r] = 0.0f;

    for (int mt = 0; mt <= nt; ++mt) {
        int m0 = mt * 64;
        __syncthreads();   // prior S reads (SV) done before K overwrite
        for (int j = tid; j < 512; j += 256) {
            int r = j >> 3, c8 = (j & 7) * 8;
            *(uint4*)&sKh[r * BP + c8] = *(const uint4*)(Khp + (size_t)(m0 + r) * HD + c8);
            *(uint4*)&sKl[r * BP + c8] = *(const uint4*)(Klp + (size_t)(m0 + r) * HD + c8);
        }
        __syncthreads();

        // ---- S = Q K^T (3-term hi/lo) ----
        float sacc[4][4];
        #pragma unroll
        for (int ni = 0; ni < 4; ni++)
            #pragma unroll
            for (int r = 0; r < 4; r++) sacc[ni][r] = 0.0f;

        #pragma unroll
        for (int ks = 0; ks < 4; ks++) {
            uint32_t ah[4], al[4], bh[2][4], bl[2][4];
            uint32_t aoff = (uint32_t)(a_row * BP + ks * 16 + a_sel) * 2u;
            ldmx4(ah[0], ah[1], ah[2], ah[3], aQh + aoff);
            ldmx4(al[0], al[1], al[2], al[3], aQl + aoff);
            #pragma unroll
            for (int p = 0; p < 2; p++) {
                uint32_t boff = (uint32_t)((bq_row + p * 16) * BP + ks * 16 + bq_col) * 2u;
                ldmx4(bh[p][0], bh[p][1], bh[p][2], bh[p][3], aKh + boff);
                ldmx4(bl[p][0], bl[p][1], bl[p][2], bl[p][3], aKl + boff);
            }
            #pragma unroll
            for (int ni = 0; ni < 4; ni++) {
                int p = ni >> 1, q2 = (ni & 1) * 2;
                mma16816(sacc[ni], ah, bh[p][q2], bh[p][q2 + 1]);
                mma16816(sacc[ni], ah, bl[p][q2], bl[p][q2 + 1]);
                mma16816(sacc[ni], al, bh[p][q2], bh[p][q2 + 1]);
            }
        }
        __syncthreads();   // K reads done before S overlay

        // ---- decay + causal, split S hi/lo into sKh/sKl ----
        #pragma unroll
        for (int ni = 0; ni < 4; ni++) {
            int col0 = wn * 32 + ni * 8 + lc2;
            #pragma unroll
            for (int half = 0; half < 2; half++) {
                int row = wm * 16 + lr + half * 8;
                int d0 = (n0 + row) - (m0 + col0);
                float v0 = 0.0f, v1 = 0.0f;
                if (d0 >= 0)     v0 = sacc[ni][half * 2 + 0] * dec[d0];
                if (d0 - 1 >= 0) v1 = sacc[ni][half * 2 + 1] * dec[d0 - 1];
                __nv_bfloat16 h0 = __float2bfloat16(v0);
                __nv_bfloat16 h1 = __float2bfloat16(v1);
                float l0 = v0 - __bfloat162float(h0);
                float l1 = v1 - __bfloat162float(h1);
                __nv_bfloat162 hv; hv.x = h0; hv.y = h1;
                __nv_bfloat162 lv; lv.x = __float2bfloat16(l0); lv.y = __float2bfloat16(l1);
                *(__nv_bfloat162*)&sKh[row * BP + col0] = hv;
                *(__nv_bfloat162*)&sKl[row * BP + col0] = lv;
            }
        }
        __syncthreads();

        // ---- Y += S V (two dd halves, V via trans ldmatrix) ----
        #pragma unroll
        for (int h2 = 0; h2 < 2; h2++) {
            {   // load V half: 64 rows x 32 cols = 256 chunks of 16B
                int j = tid;
                int r = j >> 2, c8 = (j & 3) * 8;
                *(uint4*)&sVh[r * VP + c8] =
                    *(const uint4*)(Vhp + (size_t)(m0 + r) * HD + h2 * 32 + c8);
                *(uint4*)&sVl[r * VP + c8] =
                    *(const uint4*)(Vlp + (size_t)(m0 + r) * HD + h2 * 32 + c8);
            }
            __syncthreads();
            #pragma unroll
            for (int ks = 0; ks < 4; ks++) {
                uint32_t ah[4], al[4], bh[4], bl[4];
                uint32_t aoff = (uint32_t)(a_row * BP + ks * 16 + a_sel) * 2u;
                ldmx4(ah[0], ah[1], ah[2], ah[3], aKh + aoff);
                ldmx4(al[0], al[1], al[2], al[3], aKl + aoff);
                uint32_t voff = (uint32_t)((ks * 16 + bv_row) * VP + bv_col) * 2u;
                ldmx4t(bh[0], bh[1], bh[2], bh[3], aVh + voff);
                ldmx4t(bl[0], bl[1], bl[2], bl[3], aVl + voff);
                #pragma unroll
                for (int ni2 = 0; ni2 < 2; ni2++) {
                    mma16816(yacc[h2][ni2], ah, bh[ni2 * 2], bh[ni2 * 2 + 1]);
                    mma16816(yacc[h2][ni2], ah, bl[ni2 * 2], bl[ni2 * 2 + 1]);
                    mma16816(yacc[h2][ni2], al, bh[ni2 * 2], bh[ni2 * 2 + 1]);
                }
            }
            __syncthreads();
        }
    }

    // write Y: [b, n, h*64+dd]
    #pragma unroll
    for (int h2 = 0; h2 < 2; h2++)
        #pragma unroll
        for (int ni2 = 0; ni2 < 2; ni2++) {
            int dd = h2 * 32 + wn * 16 + ni2 * 8 + lc2;
            #pragma unroll
            for (int half = 0; half < 2; half++) {
                int row = wm * 16 + lr + half * 8;
                float2 o;
                o.x = yacc[h2][ni2][half * 2 + 0];
                o.y = yacc[h2][ni2][half * 2 + 1];
                *(float2*)&g_Y[(size_t)(b * NSEQ + n0 + row) * DIM + h * HD + dd] = o;
            }
        }
}

// ---------------- LN(y)*silu(g) + per-row double partials ----------------
__global__ void k_lng(const float* __restrict__ lnw, const float* __restrict__ lnb) {
    int row = blockIdx.x;
    const float* y = g_Y + (size_t)row * DIM;
    int c0 = threadIdx.x * 4;
    float4 yv = *(const float4*)(y + c0);

    __shared__ double shs[256], shq[256];
    shs[threadIdx.x] = (double)yv.x + yv.y + yv.z + yv.w;
    shq[threadIdx.x] = (double)yv.x*yv.x + (double)yv.y*yv.y
                     + (double)yv.z*yv.z + (double)yv.w*yv.w;
    __syncthreads();
    for (int o = 128; o > 0; o >>= 1) {
        if (threadIdx.x < o) {
            shs[threadIdx.x] += shs[threadIdx.x + o];
            shq[threadIdx.x] += shq[threadIdx.x + o];
        }
        __syncthreads();
    }
    double mu_d  = shs[0] / (double)DIM;
    double var_d = shq[0] / (double)DIM - mu_d * mu_d;
    float mu = (float)mu_d;
    float rs = (float)(1.0 / sqrt(var_d + 1e-5));
    __syncthreads();

    float4 g4 = *(const float4*)(g_G + (size_t)row * DIM + c0);
    float4 w4 = *(const float4*)(lnw + c0);
    float4 b4 = *(const float4*)(lnb + c0);
    float4 z;
    z.x = ((yv.x - mu) * rs * w4.x + b4.x) * g4.x;
    z.y = ((yv.y - mu) * rs * w4.y + b4.y) * g4.y;
    z.z = ((yv.z - mu) * rs * w4.z + b4.z) * g4.z;
    z.w = ((yv.w - mu) * rs * w4.w + b4.w) * g4.w;
    *(float4*)(g_Z + (size_t)row * DIM + c0) = z;

    shs[threadIdx.x] = (double)z.x + z.y + z.z + z.w;
    shq[threadIdx.x] = (double)z.x*z.x + (double)z.y*z.y
                     + (double)z.z*z.z + (double)z.w*z.w;
    __syncthreads();
    for (int o = 128; o > 0; o >>= 1) {
        if (threadIdx.x < o) {
            shs[threadIdx.x] += shs[threadIdx.x + o];
            shq[threadIdx.x] += shq[threadIdx.x + o];
        }
        __syncthreads();
    }
    if (threadIdx.x == 0) {
        g_zpart_s[row] = shs[0];
        g_zpart_q[row] = shq[0];
    }
}

__global__ void k_fin2() {
    int b = blockIdx.x;
    double s = 0.0, q = 0.0;
    for (int i = threadIdx.x; i < NSEQ; i += 256) {
        s += g_zpart_s[b * NSEQ + i];
        q += g_zpart_q[b * NSEQ + i];
    }
    __shared__ double shs[256], shq[256];
    shs[threadIdx.x] = s; shq[threadIdx.x] = q; __syncthreads();
    for (int o = 128; o > 0; o >>= 1) {
        if (threadIdx.x < o) {
            shs[threadIdx.x] += shs[threadIdx.x + o];
            shq[threadIdx.x] += shq[threadIdx.x + o];
        }
        __syncthreads();
    }
    if (threadIdx.x == 0) {
        double n = (double)BELEMS;
        double mu = shs[0] / n;
        double var = shq[0] / n - mu * mu;
        g_zmu[b]   = (float)mu;
        g_zrstd[b] = (float)(1.0 / sqrt(var + 1e-5));
    }
}

// ---------------- launch ----------------
extern "C" void kernel_launch(void* const* d_in, const int* in_sizes, int n_in,
                              void* d_out, int out_size) {
    (void)in_sizes; (void)n_in; (void)out_size;
    const float* x   = (const float*)d_in[0];
    const float* wq  = (const float*)d_in[1];
    const float* wk  = (const float*)d_in[2];
    const float* wv  = (const float*)d_in[3];
    const float* wg  = (const float*)d_in[4];
    const float* wo  = (const float*)d_in[5];
    const float* lnw = (const float*)d_in[6];
    const float* lnb = (const float*)d_in[7];
    float* out = (float*)d_out;

    k_reduce_x   <<<dim3(64, BATCH), 256>>>(x);
    k_reduce_wabs<<<dim3(64, 5),     256>>>(wq, wk, wv, wg, wo);
    k_fin1       <<<1, 32>>>();
    k_tern       <<<dim3(256, 5),    256>>>(wq, wk, wv, wg, wo);
    k_qact       <<<ROWS, 256>>>(x, 0);
    k_decay      <<<NH, 256>>>();
    k_gemm_mma   <<<dim3(8, 32, 4),  256>>>(0, out);   // Q,K,V,G
    k_attn_mma   <<<dim3(NSEQ/64, NH, BATCH), 256>>>();
    k_lng        <<<ROWS, 256>>>(lnw, lnb);
    k_fin2       <<<BATCH, 256>>>();
    k_qact       <<<ROWS, 256>>>(x, 1);                // quantize z
    k_gemm_mma   <<<dim3(8, 32, 1),  256>>>(4, out);   // final projection
}